// round 6
// baseline (speedup 1.0000x reference)
#include <cuda_runtime.h>

// GarNet: B=256, V=1024, F=16, P=16, A=8, NF=32
// out[b,v,n] = mask(v) * ( sum_a ew[v,a] * M[b,a,n] + b_out[n] )
//   ew[v,a]  = mask(v) * 2^(-(data[v]·W_s + b_s)[a])
//   agg[a,p] = (1/V) sum_v ew[v,a] * (data[v]·W_flr + b_flr)[p]
//   M[a,n]   = sum_p agg[a,p] * W_out[a*P+p, n]
//
// K1 (4x256 x128t): 2 v/thread feat+ew (f32x2, weights in __constant__),
//                   ew->scratch, f32x2 quad-product block reduction.
// Km (256 x128t):   partials -> agg -> M.
// K2 (8x256 x128t): out = mask*(ew @ M + b_out), M in registers.

#define NB   256
#define NV   1024
#define NFEA 16
#define NP   16
#define NA   8
#define NOUT 32

#define K1S  4
#define K1V  256
#define K2S  8
#define K2V  128

#define RS   258      // ull stride per pair-row (256 + 2)

__device__ float g_ew[NB * NV * NA];          // 8 MB
__device__ float g_part[NB * K1S * 128];      // 512 KB
__device__ float g_M[NB * NA * NOUT];         // 256 KB

// weights in constant memory (filled by async D2D copies in kernel_launch)
__constant__ ulonglong2          c_Wf2[64];   // W_flr [16k][16p] as p-pairs
__constant__ ulonglong2          c_Ws2[32];   // W_s   [16k][8a]  as a-pairs
__constant__ unsigned long long  c_bf2[8];
__constant__ unsigned long long  c_bs2[4];

#define FMA_F32X2(d, a, b, c) \
    asm("fma.rn.f32x2 %0, %1, %2, %3;" : "=l"(d) : "l"(a), "l"(b), "l"(c))
#define PACK2_SAME(out, x) \
    asm("mov.b64 %0, {%1, %1};" : "=l"(out) : "r"(__float_as_uint(x)))
#define PACK2(out, lo, hi) \
    asm("mov.b64 %0, {%1, %2};" : "=l"(out) : "r"(__float_as_uint(lo)), "r"(__float_as_uint(hi)))
#define UNPACK2(lo, hi, in) \
    asm("mov.b64 {%0, %1}, %2;" : "=r"(lo), "=r"(hi) : "l"(in))

// ==================== K1 ====================
__global__ void __launch_bounds__(128, 5)
garnet_k1(const float* __restrict__ data,
          const int*   __restrict__ num_vertex)
{
    __shared__ __align__(16) unsigned long long red2[12 * RS]; // 4 ew-pair + 8 feat-pair rows
    __shared__ __align__(16) unsigned long long comb[32 * 8];  // 32 quads x 4 vsplit x 2

    const int t = threadIdx.x;
    const int s = blockIdx.x;
    const int b = blockIdx.y;
    const int v0 = s * K1V + t;
    const int v1 = v0 + 128;

    // ---- hoisted global loads (MLP 8 up front) ----
    const float4* d40 = reinterpret_cast<const float4*>(data) + ((size_t)b * NV + v0) * 4;
    const float4* d41 = reinterpret_cast<const float4*>(data) + ((size_t)b * NV + v1) * 4;
    float4 qa0 = d40[0], qa1 = d40[1], qa2 = d40[2], qa3 = d40[3];
    float4 qb0 = d41[0], qb1 = d41[1], qb2 = d41[2], qb3 = d41[3];
    const int nv = num_vertex[b];

    float xa[16] = {qa0.x,qa0.y,qa0.z,qa0.w, qa1.x,qa1.y,qa1.z,qa1.w,
                    qa2.x,qa2.y,qa2.z,qa2.w, qa3.x,qa3.y,qa3.z,qa3.w};
    float xb[16] = {qb0.x,qb0.y,qb0.z,qb0.w, qb1.x,qb1.y,qb1.z,qb1.w,
                    qb2.x,qb2.y,qb2.z,qb2.w, qb3.x,qb3.y,qb3.z,qb3.w};

    // packed accumulators
    unsigned long long f2a[8], f2b[8], sd2a[4], sd2b[4];
    #pragma unroll
    for (int j = 0; j < 8; ++j) { f2a[j] = c_bf2[j]; f2b[j] = c_bf2[j]; }
    #pragma unroll
    for (int j = 0; j < 4; ++j) { sd2a[j] = c_bs2[j]; sd2b[j] = c_bs2[j]; }

    #pragma unroll
    for (int k = 0; k < 16; ++k) {
        unsigned long long xpa, xpb;
        PACK2_SAME(xpa, xa[k]);
        PACK2_SAME(xpb, xb[k]);
        const ulonglong2 w0 = c_Wf2[k*4+0], w1 = c_Wf2[k*4+1];
        const ulonglong2 w2 = c_Wf2[k*4+2], w3 = c_Wf2[k*4+3];
        FMA_F32X2(f2a[0], xpa, w0.x, f2a[0]);  FMA_F32X2(f2b[0], xpb, w0.x, f2b[0]);
        FMA_F32X2(f2a[1], xpa, w0.y, f2a[1]);  FMA_F32X2(f2b[1], xpb, w0.y, f2b[1]);
        FMA_F32X2(f2a[2], xpa, w1.x, f2a[2]);  FMA_F32X2(f2b[2], xpb, w1.x, f2b[2]);
        FMA_F32X2(f2a[3], xpa, w1.y, f2a[3]);  FMA_F32X2(f2b[3], xpb, w1.y, f2b[3]);
        FMA_F32X2(f2a[4], xpa, w2.x, f2a[4]);  FMA_F32X2(f2b[4], xpb, w2.x, f2b[4]);
        FMA_F32X2(f2a[5], xpa, w2.y, f2a[5]);  FMA_F32X2(f2b[5], xpb, w2.y, f2b[5]);
        FMA_F32X2(f2a[6], xpa, w3.x, f2a[6]);  FMA_F32X2(f2b[6], xpb, w3.x, f2b[6]);
        FMA_F32X2(f2a[7], xpa, w3.y, f2a[7]);  FMA_F32X2(f2b[7], xpb, w3.y, f2b[7]);
        const ulonglong2 u0 = c_Ws2[k*2+0], u1 = c_Ws2[k*2+1];
        FMA_F32X2(sd2a[0], xpa, u0.x, sd2a[0]);  FMA_F32X2(sd2b[0], xpb, u0.x, sd2b[0]);
        FMA_F32X2(sd2a[1], xpa, u0.y, sd2a[1]);  FMA_F32X2(sd2b[1], xpb, u0.y, sd2b[1]);
        FMA_F32X2(sd2a[2], xpa, u1.x, sd2a[2]);  FMA_F32X2(sd2b[2], xpb, u1.x, sd2b[2]);
        FMA_F32X2(sd2a[3], xpa, u1.y, sd2a[3]);  FMA_F32X2(sd2b[3], xpb, u1.y, sd2b[3]);
    }

    // ---- ew = mask * 2^(-dist) ----
    const bool ma = (v0 < nv), mb = (v1 < nv);
    float ewa[8], ewb[8];
    #pragma unroll
    for (int j = 0; j < 4; ++j) {
        unsigned int lo, hi;
        UNPACK2(lo, hi, sd2a[j]);
        ewa[2*j]   = ma ? exp2f(-__uint_as_float(lo)) : 0.0f;
        ewa[2*j+1] = ma ? exp2f(-__uint_as_float(hi)) : 0.0f;
        UNPACK2(lo, hi, sd2b[j]);
        ewb[2*j]   = mb ? exp2f(-__uint_as_float(lo)) : 0.0f;
        ewb[2*j+1] = mb ? exp2f(-__uint_as_float(hi)) : 0.0f;
    }

    // ew -> global scratch
    float4* e4a = reinterpret_cast<float4*>(g_ew + ((size_t)b * NV + v0) * NA);
    float4* e4b = reinterpret_cast<float4*>(g_ew + ((size_t)b * NV + v1) * NA);
    e4a[0] = make_float4(ewa[0], ewa[1], ewa[2], ewa[3]);
    e4a[1] = make_float4(ewa[4], ewa[5], ewa[6], ewa[7]);
    e4b[0] = make_float4(ewb[0], ewb[1], ewb[2], ewb[3]);
    e4b[1] = make_float4(ewb[4], ewb[5], ewb[6], ewb[7]);

    // ---- stage pair-rows (STS.64) ----
    #pragma unroll
    for (int j = 0; j < 4; ++j) {
        unsigned long long ea, eb;
        PACK2(ea, ewa[2*j], ewa[2*j+1]);
        PACK2(eb, ewb[2*j], ewb[2*j+1]);
        red2[j * RS + t]       = ea;
        red2[j * RS + t + 128] = eb;
    }
    #pragma unroll
    for (int j = 0; j < 8; ++j) {
        red2[(4 + j) * RS + t]       = f2a[j];
        red2[(4 + j) * RS + t + 128] = f2b[j];
    }
    __syncthreads();

    // ---- quad reduction: thread t -> quad q (a-pair, p-pair), v-split vs ----
    {
        const int q  = t >> 2;            // 0..31
        const int vs = t & 3;             // 0..3
        const int apair = q >> 3;         // 0..3
        const int ppair = q & 7;          // 0..7
        const unsigned long long* er = &red2[apair * RS];
        const unsigned long long* fr = &red2[(4 + ppair) * RS];

        unsigned long long acc0 = 0ull, acc1 = 0ull;   // (0.f,0.f) packed
        #pragma unroll
        for (int i = 0; i < 32; ++i) {
            const int col = vs * 2 + i * 8;            // bank-staggered columns
            const ulonglong2 e2 = *reinterpret_cast<const ulonglong2*>(er + col);
            const ulonglong2 f2 = *reinterpret_cast<const ulonglong2*>(fr + col);
            unsigned int lo, hi;
            unsigned long long d0, d1;
            UNPACK2(lo, hi, e2.x);
            PACK2_SAME(d0, __uint_as_float(lo));
            PACK2_SAME(d1, __uint_as_float(hi));
            FMA_F32X2(acc0, d0, f2.x, acc0);
            FMA_F32X2(acc1, d1, f2.x, acc1);
            UNPACK2(lo, hi, e2.y);
            PACK2_SAME(d0, __uint_as_float(lo));
            PACK2_SAME(d1, __uint_as_float(hi));
            FMA_F32X2(acc0, d0, f2.y, acc0);
            FMA_F32X2(acc1, d1, f2.y, acc1);
        }
        comb[q * 8 + vs * 2 + 0] = acc0;
        comb[q * 8 + vs * 2 + 1] = acc1;
    }
    __syncthreads();

    // ---- final combine: thread t -> (a = t>>4, p = t&15) ----
    {
        const int a = t >> 4, p = t & 15;
        const int qq = (a >> 1) * 8 + (p >> 1);
        const float* cf = reinterpret_cast<const float*>(comb);
        float ssum = 0.f;
        #pragma unroll
        for (int vs = 0; vs < 4; ++vs)
            ssum += cf[(qq * 8 + vs * 2 + (a & 1)) * 2 + (p & 1)];
        g_part[((size_t)b * K1S + s) * 128 + t] = ssum;
    }
}

// ==================== Km ====================
__global__ void __launch_bounds__(128)
garnet_km(const float* __restrict__ W_out)
{
    __shared__ float agg_sh[128];
    __shared__ float Wo_sh[NA * NP * NOUT];

    const int t = threadIdx.x;
    const int b = blockIdx.x;

    {
        const float4* src = reinterpret_cast<const float4*>(W_out);
        float4* dst = reinterpret_cast<float4*>(Wo_sh);
        #pragma unroll
        for (int i = 0; i < 8; ++i) dst[t + i * 128] = src[t + i * 128];
    }

    float acc = 0.f;
    #pragma unroll
    for (int sp = 0; sp < K1S; ++sp)
        acc += g_part[((size_t)b * K1S + sp) * 128 + t];
    agg_sh[t] = acc * (1.0f / (float)NV);
    __syncthreads();

    #pragma unroll
    for (int e = t; e < 256; e += 128) {
        const int a = e >> 5, n = e & 31;
        float mm = 0.f;
        #pragma unroll
        for (int p = 0; p < 16; ++p)
            mm += agg_sh[a * 16 + p] * Wo_sh[(a * 16 + p) * 32 + n];
        g_M[b * 256 + e] = mm;
    }
}

// ==================== K2 ====================
__global__ void __launch_bounds__(128)
garnet_k2(const int*   __restrict__ num_vertex,
          const float* __restrict__ b_out,
          float*       __restrict__ out)
{
    __shared__ float4 ew4_sh[K2V * 2];
    __shared__ float4 M4_sh[64];

    const int t  = threadIdx.x;
    const int s  = blockIdx.x;
    const int b  = blockIdx.y;
    const int ng = t & 7;
    const int vl = t >> 3;

    {
        const float4* src = reinterpret_cast<const float4*>(g_ew)
                          + ((size_t)b * NV + s * K2V) * 2;
        ew4_sh[t]       = src[t];
        ew4_sh[t + 128] = src[t + 128];
        if (t < 64)
            M4_sh[t] = reinterpret_cast<const float4*>(g_M + b * 256)[t];
    }
    const int nv = num_vertex[b];
    const float4 bo = reinterpret_cast<const float4*>(b_out)[ng];
    __syncthreads();

    float4 Mr[8];
    #pragma unroll
    for (int a = 0; a < 8; ++a) Mr[a] = M4_sh[a * 8 + ng];

    float4* out4 = reinterpret_cast<float4*>(out)
                 + ((size_t)b * NV + s * K2V) * (NOUT / 4);
    const float4 z = make_float4(0.f, 0.f, 0.f, 0.f);

    #pragma unroll
    for (int k = 0; k < 8; ++k) {
        const int v = vl + k * 16;
        const float4 e0 = ew4_sh[v * 2];
        const float4 e1 = ew4_sh[v * 2 + 1];

        float4 acc = bo;
        acc.x += e0.x*Mr[0].x; acc.y += e0.x*Mr[0].y; acc.z += e0.x*Mr[0].z; acc.w += e0.x*Mr[0].w;
        acc.x += e0.y*Mr[1].x; acc.y += e0.y*Mr[1].y; acc.z += e0.y*Mr[1].z; acc.w += e0.y*Mr[1].w;
        acc.x += e0.z*Mr[2].x; acc.y += e0.z*Mr[2].y; acc.z += e0.z*Mr[2].z; acc.w += e0.z*Mr[2].w;
        acc.x += e0.w*Mr[3].x; acc.y += e0.w*Mr[3].y; acc.z += e0.w*Mr[3].z; acc.w += e0.w*Mr[3].w;
        acc.x += e1.x*Mr[4].x; acc.y += e1.x*Mr[4].y; acc.z += e1.x*Mr[4].z; acc.w += e1.x*Mr[4].w;
        acc.x += e1.y*Mr[5].x; acc.y += e1.y*Mr[5].y; acc.z += e1.y*Mr[5].z; acc.w += e1.y*Mr[5].w;
        acc.x += e1.z*Mr[6].x; acc.y += e1.z*Mr[6].y; acc.z += e1.z*Mr[6].z; acc.w += e1.z*Mr[6].w;
        acc.x += e1.w*Mr[7].x; acc.y += e1.w*Mr[7].y; acc.z += e1.w*Mr[7].z; acc.w += e1.w*Mr[7].w;

        out4[v * 8 + ng] = (s * K2V + v < nv) ? acc : z;
    }
}

extern "C" void kernel_launch(void* const* d_in, const int* in_sizes, int n_in,
                              void* d_out, int out_size)
{
    const float* data       = (const float*)d_in[0];
    const int*   num_vertex = (const int*)  d_in[1];
    const float* W_flr      = (const float*)d_in[2];
    const float* b_flr      = (const float*)d_in[3];
    const float* W_s        = (const float*)d_in[4];
    const float* b_s        = (const float*)d_in[5];
    const float* W_out      = (const float*)d_in[6];
    const float* b_out      = (const float*)d_in[7];
    float*       out        = (float*)d_out;

    (void)in_sizes; (void)n_in; (void)out_size;

    // weights -> constant memory (async D2D, graph-capturable)
    cudaMemcpyToSymbolAsync(c_Wf2, W_flr, 256 * sizeof(float), 0, cudaMemcpyDeviceToDevice);
    cudaMemcpyToSymbolAsync(c_Ws2, W_s,   128 * sizeof(float), 0, cudaMemcpyDeviceToDevice);
    cudaMemcpyToSymbolAsync(c_bf2, b_flr,  16 * sizeof(float), 0, cudaMemcpyDeviceToDevice);
    cudaMemcpyToSymbolAsync(c_bs2, b_s,     8 * sizeof(float), 0, cudaMemcpyDeviceToDevice);

    dim3 g1(K1S, NB), g2(K2S, NB);
    garnet_k1<<<g1, 128>>>(data, num_vertex);
    garnet_km<<<NB, 128>>>(W_out);
    garnet_k2<<<g2, 128>>>(num_vertex, b_out, out);
}